// round 1
// baseline (speedup 1.0000x reference)
#include <cuda_runtime.h>

// SVConv2d: out[n,o,h,w] = bias[o] + sum_{ci,kh,kw} x[n,ci,h+kh-1,w+kw-1] * W[o,ci,kh,kw,h,w]
// N=8, Cin=Cout=32, K=3, H=W=64. Weight (151 MB) streams once from DRAM -> DRAM-bound.

#define TW 16
#define TH 8
#define CPB 4  // couts per block

__device__ __forceinline__ unsigned long long pack2(float a, float b) {
    unsigned long long r;
    asm("mov.b64 %0, {%1, %2};" : "=l"(r) : "f"(a), "f"(b));
    return r;
}
__device__ __forceinline__ void fma2(unsigned long long& d, unsigned long long a, unsigned long long b) {
    asm("fma.rn.f32x2 %0, %1, %2, %0;" : "+l"(d) : "l"(a), "l"(b));
}
__device__ __forceinline__ float2 unpack2(unsigned long long v) {
    float x, y;
    asm("mov.b64 {%0, %1}, %2;" : "=f"(x), "=f"(y) : "l"(v));
    return make_float2(x, y);
}

__global__ __launch_bounds__(TW * TH)
void svconv_kernel(const float* __restrict__ x,
                   const float* __restrict__ weight,
                   const float* __restrict__ bias,
                   float* __restrict__ out) {
    constexpr int N = 8, Cin = 32, Cout = 32, H = 64, W = 64;
    constexpr int HR = TH + 2, WR = TW + 2;  // halo tile 10 x 18

    // Two float4 planes: xs0 = n0..3, xs1 = n4..7. 16-byte col stride ->
    // conflict-free LDS.128 (8 lanes x 16B = one 128B phase).
    __shared__ float4 xs0[HR][WR];
    __shared__ float4 xs1[HR][WR];

    const int tx = threadIdx.x, ty = threadIdx.y;
    const int tid = ty * TW + tx;
    const int w0 = blockIdx.x * TW;
    const int h0 = blockIdx.y * TH;
    const int c0 = blockIdx.z * CPB;
    const int h = h0 + ty, w = w0 + tx;

    unsigned long long acc[CPB][4];
#pragma unroll
    for (int c = 0; c < CPB; c++)
#pragma unroll
        for (int j = 0; j < 4; j++) acc[c][j] = 0ull;

    for (int cin = 0; cin < Cin; cin++) {
        // ---- stage x halo tile for this cin (all 8 n) ----
        for (int i = tid; i < N * HR * WR; i += TW * TH) {
            int n = i / (HR * WR);
            int rc = i % (HR * WR);
            int r = rc / WR, c = rc % WR;
            int gh = h0 + r - 1, gw = w0 + c - 1;
            float v = 0.0f;
            if ((unsigned)gh < (unsigned)H && (unsigned)gw < (unsigned)W)
                v = x[((n * Cin + cin) * H + gh) * W + gw];
            if (n < 4)
                ((float*)&xs0[r][c])[n] = v;
            else
                ((float*)&xs1[r][c])[n - 4] = v;
        }
        __syncthreads();

        // weight base for this (c0, cin) at spatial (h, w)
        const float* wp = weight + (size_t)(c0 * Cin + cin) * 9 * (H * W) + h * W + w;

#pragma unroll
        for (int k = 0; k < 9; k++) {
            const int kh = k / 3, kw = k % 3;
            float4 lo = xs0[ty + kh][tx + kw];
            float4 hi = xs1[ty + kh][tx + kw];
            unsigned long long xq0 = pack2(lo.x, lo.y);
            unsigned long long xq1 = pack2(lo.z, lo.w);
            unsigned long long xq2 = pack2(hi.x, hi.y);
            unsigned long long xq3 = pack2(hi.z, hi.w);
#pragma unroll
            for (int c = 0; c < CPB; c++) {
                // stream weight past L2 (used once), keep x resident in L2
                float wv = __ldcs(wp + (size_t)(c * Cin * 9 + k) * (H * W));
                unsigned long long wd = pack2(wv, wv);
                fma2(acc[c][0], wd, xq0);
                fma2(acc[c][1], wd, xq1);
                fma2(acc[c][2], wd, xq2);
                fma2(acc[c][3], wd, xq3);
            }
        }
        __syncthreads();
    }

    // ---- epilogue: add bias, write all 8 n x 4 couts ----
#pragma unroll
    for (int c = 0; c < CPB; c++) {
        float b = bias[c0 + c];
#pragma unroll
        for (int j = 0; j < 4; j++) {
            float2 v = unpack2(acc[c][j]);
            int n0 = 2 * j, n1 = 2 * j + 1;
            out[((n0 * Cout + (c0 + c)) * H + h) * W + w] = v.x + b;
            out[((n1 * Cout + (c0 + c)) * H + h) * W + w] = v.y + b;
        }
    }
}

extern "C" void kernel_launch(void* const* d_in, const int* in_sizes, int n_in,
                              void* d_out, int out_size) {
    const float* x = (const float*)d_in[0];
    const float* wgt = (const float*)d_in[1];
    const float* bias = (const float*)d_in[2];
    float* out = (float*)d_out;

    dim3 grid(64 / TW, 64 / TH, 32 / CPB);  // 4 x 8 x 8 = 256 blocks
    dim3 block(TW, TH);                     // 128 threads
    svconv_kernel<<<grid, block>>>(x, wgt, bias, out);
}